// round 4
// baseline (speedup 1.0000x reference)
#include <cuda_runtime.h>

// Chebyshev-KAN: out[b] = sum_d sum_{k=0..8} coeff[d*9+k] * T_k(x[b,d])
// x: (16384, 512) f32; coeff: (4608,) f32; out: (16384,) f32.
//
// R4: persistent grid-stride CTAs + software-pipelined tile loads.
// 740 CTAs (148 SM x 5), 128 threads each (4 warps; warp g owns dims
// [g*128,(g+1)*128), 4 dims/lane, monomial coeffs in packed-f32x2 regs).
// Tiles of 4 rows; double-buffered LDG.128 so next tile's loads are in
// flight during current tile's FMA/shuffle work. One syncthreads per tile
// (parity-buffered smem partials).

#define BATCH    16384
#define DIM      512
#define NDEG     9
#define THREADS  128
#define TILE     4
#define NTILES   (BATCH / TILE)      // 4096
#define GRID     740                 // 148 SMs x 5 resident CTAs

typedef unsigned long long ull;

__device__ __forceinline__ ull pack2(float lo, float hi) {
    ull r; asm("mov.b64 %0, {%1, %2};" : "=l"(r) : "f"(lo), "f"(hi)); return r;
}
__device__ __forceinline__ void unpack2(ull v, float& lo, float& hi) {
    asm("mov.b64 {%0, %1}, %2;" : "=f"(lo), "=f"(hi) : "l"(v));
}
__device__ __forceinline__ ull fma2(ull a, ull b, ull c) {
    ull r; asm("fma.rn.f32x2 %0, %1, %2, %3;" : "=l"(r) : "l"(a), "l"(b), "l"(c)); return r;
}
__device__ __forceinline__ ull add2(ull a, ull b) {
    ull r; asm("add.rn.f32x2 %0, %1, %2;" : "=l"(r) : "l"(a), "l"(b)); return r;
}

// Chebyshev coeffs c[0..8] -> monomial coeffs a[0..8].
__device__ __forceinline__ void cheb2mono(const float* __restrict__ c, float* a) {
    a[8] = 128.0f * c[8];
    a[7] =  64.0f * c[7];
    a[6] = fmaf(-256.0f, c[8], 32.0f * c[6]);
    a[5] = fmaf(-112.0f, c[7], 16.0f * c[5]);
    a[4] = fmaf(160.0f, c[8], fmaf(-48.0f, c[6], 8.0f * c[4]));
    a[3] = fmaf( 56.0f, c[7], fmaf(-20.0f, c[5], 4.0f * c[3]));
    a[2] = fmaf(-32.0f, c[8], fmaf(18.0f, c[6], fmaf(-8.0f, c[4], 2.0f * c[2])));
    a[1] = fmaf( -7.0f, c[7], fmaf( 5.0f, c[5], fmaf(-3.0f, c[3], c[1])));
    a[0] = ((c[0] - c[2]) + (c[4] - c[6])) + c[8];
}

__device__ __forceinline__ float eval4(float4 xv, const ull* A, const ull* B) {
    ull xA = pack2(xv.x, xv.y);
    ull xB = pack2(xv.z, xv.w);
    ull p = A[8], q = B[8];
    #pragma unroll
    for (int k = 7; k >= 0; --k) {
        p = fma2(p, xA, A[k]);
        q = fma2(q, xB, B[k]);
    }
    ull s = add2(p, q);
    float lo, hi; unpack2(s, lo, hi);
    return lo + hi;
}

struct Ctx {
    const float4* xrow;
    float* out;
    int lane, g, col4;
};

// Process one 4-row tile from buffer xv; uses smem parity buffer P.
template <int P>
__device__ __forceinline__ void process_tile(
    const Ctx& c, const float4* xv, const ull* A, const ull* B,
    int t, float (*s_part)[TILE][4])
{
    float acc[TILE];
    #pragma unroll
    for (int r = 0; r < TILE; ++r) acc[r] = eval4(xv[r], A, B);

    #pragma unroll
    for (int off = 16; off; off >>= 1) {
        #pragma unroll
        for (int r = 0; r < TILE; ++r)
            acc[r] += __shfl_xor_sync(0xffffffffu, acc[r], off);
    }
    if (c.lane == 0) {
        #pragma unroll
        for (int r = 0; r < TILE; ++r) s_part[P][r][c.g] = acc[r];
    }
    __syncthreads();
    const int tid = threadIdx.x;
    if (tid < TILE) {
        float4 v = *reinterpret_cast<const float4*>(s_part[P][tid]);
        c.out[t * TILE + tid] = (v.x + v.y) + (v.z + v.w);
    }
    // no trailing sync: next tile writes the other parity buffer; the sync
    // inside the next process_tile orders reuse of this one.
}

__device__ __forceinline__ void load_tile(const Ctx& c, float4* xv, int t) {
    const float4* p = c.xrow + (size_t)t * (TILE * (DIM / 4)) + c.col4;
    #pragma unroll
    for (int r = 0; r < TILE; ++r)
        xv[r] = __ldcs(p + r * (DIM / 4));
}

__global__ __launch_bounds__(THREADS, 5)
void kan_cheb_kernel(const float* __restrict__ x,
                     const float* __restrict__ coeff,
                     float* __restrict__ out)
{
    __shared__ __align__(16) float s_part[2][TILE][4];

    const int tid  = threadIdx.x;
    Ctx c;
    c.lane = tid & 31;
    c.g    = tid >> 5;
    c.col4 = (c.g * 128 + c.lane * 4) >> 2;
    c.xrow = reinterpret_cast<const float4*>(x);
    c.out  = out;

    // ---- prologue: 36 coeffs -> monomial -> packed f32x2 registers ----
    const int d0 = c.g * 128 + c.lane * 4;
    float cf[36];
    {
        const float4* c4 = reinterpret_cast<const float4*>(coeff + d0 * NDEG);
        #pragma unroll
        for (int i = 0; i < 9; ++i) {
            float4 v = c4[i];
            cf[4*i+0] = v.x; cf[4*i+1] = v.y; cf[4*i+2] = v.z; cf[4*i+3] = v.w;
        }
    }
    ull A[9], B[9];
    {
        float t0[9], t1[9];
        cheb2mono(cf + 0,  t0); cheb2mono(cf + 9,  t1);
        #pragma unroll
        for (int k = 0; k < 9; ++k) A[k] = pack2(t0[k], t1[k]);
        cheb2mono(cf + 18, t0); cheb2mono(cf + 27, t1);
        #pragma unroll
        for (int k = 0; k < 9; ++k) B[k] = pack2(t0[k], t1[k]);
    }

    // ---- grid-stride tile loop, 2-deep software pipeline ----
    float4 xa[TILE], xb[TILE];
    int t = blockIdx.x;
    if (t >= NTILES) return;
    load_tile(c, xa, t);

    for (;;) {
        int tn = t + GRID;
        if (tn < NTILES) load_tile(c, xb, tn);
        process_tile<0>(c, xa, A, B, t, s_part);
        t = tn;
        if (t >= NTILES) break;

        tn = t + GRID;
        if (tn < NTILES) load_tile(c, xa, tn);
        process_tile<1>(c, xb, A, B, t, s_part);
        t = tn;
        if (t >= NTILES) break;
    }
}

extern "C" void kernel_launch(void* const* d_in, const int* in_sizes, int n_in,
                              void* d_out, int out_size)
{
    const float* x     = (const float*)d_in[0];
    const float* coeff = (const float*)d_in[1];
    // d_in[2] = degree (int32, fixed at 8) — baked in at compile time.
    float* out = (float*)d_out;

    kan_cheb_kernel<<<GRID, THREADS>>>(x, coeff, out);
}

// round 5
// speedup vs baseline: 1.0239x; 1.0239x over previous
#include <cuda_runtime.h>

// Chebyshev-KAN: out[b] = sum_d sum_{k=0..8} coeff[d*9+k] * T_k(x[b,d])
// x: (16384, 512) f32; coeff: (4608,) f32; out: (16384,) f32.
//
// R5: occupancy play. 2 dims/thread (one packed-f32x2 Horner chain, 9 ull
// coef regs), 256 threads/block = full 512-dim row, 8 rows per block
// front-batched as 8 LDG.64. __launch_bounds__(256,4) caps regs at 64 ->
// 32 warps/SM (50% occ), ~64KB in flight per SM.

#define BATCH    16384
#define DIM      512
#define NDEG     9
#define THREADS  256
#define TILE     8
#define GRID     (BATCH / TILE)      // 2048

typedef unsigned long long ull;

__device__ __forceinline__ ull pack2(float lo, float hi) {
    ull r; asm("mov.b64 %0, {%1, %2};" : "=l"(r) : "f"(lo), "f"(hi)); return r;
}
__device__ __forceinline__ void unpack2(ull v, float& lo, float& hi) {
    asm("mov.b64 {%0, %1}, %2;" : "=f"(lo), "=f"(hi) : "l"(v));
}
__device__ __forceinline__ ull fma2(ull a, ull b, ull c) {
    ull r; asm("fma.rn.f32x2 %0, %1, %2, %3;" : "=l"(r) : "l"(a), "l"(b), "l"(c)); return r;
}

// Chebyshev coeffs c[0..8] -> monomial coeffs a[0..8].
__device__ __forceinline__ void cheb2mono(const float* __restrict__ c, float* a) {
    a[8] = 128.0f * c[8];
    a[7] =  64.0f * c[7];
    a[6] = fmaf(-256.0f, c[8], 32.0f * c[6]);
    a[5] = fmaf(-112.0f, c[7], 16.0f * c[5]);
    a[4] = fmaf(160.0f, c[8], fmaf(-48.0f, c[6], 8.0f * c[4]));
    a[3] = fmaf( 56.0f, c[7], fmaf(-20.0f, c[5], 4.0f * c[3]));
    a[2] = fmaf(-32.0f, c[8], fmaf(18.0f, c[6], fmaf(-8.0f, c[4], 2.0f * c[2])));
    a[1] = fmaf( -7.0f, c[7], fmaf( 5.0f, c[5], fmaf(-3.0f, c[3], c[1])));
    a[0] = ((c[0] - c[2]) + (c[4] - c[6])) + c[8];
}

__global__ __launch_bounds__(THREADS, 4)
void kan_cheb_kernel(const float* __restrict__ x,
                     const float* __restrict__ coeff,
                     float* __restrict__ out)
{
    __shared__ float s_part[TILE][8];     // [row][warp]

    const int tid  = threadIdx.x;
    const int lane = tid & 31;
    const int w    = tid >> 5;            // warp 0..7
    const int d0   = w * 64 + lane * 2;   // 2 dims per thread
    const int col2 = d0 >> 1;             // float2 column (row = 256 float2)

    // ---- prologue: 18 coeffs (9 x LDG.64) -> monomial -> 9 packed regs ----
    float cf[18];
    {
        const float2* c2 = reinterpret_cast<const float2*>(coeff + d0 * NDEG);
        #pragma unroll
        for (int i = 0; i < 9; ++i) {
            float2 v = c2[i];
            cf[2 * i] = v.x; cf[2 * i + 1] = v.y;
        }
    }
    ull A[9];
    {
        float t0[9], t1[9];
        cheb2mono(cf, t0);
        cheb2mono(cf + 9, t1);
        #pragma unroll
        for (int k = 0; k < 9; ++k) A[k] = pack2(t0[k], t1[k]);
    }

    const int rowbase = blockIdx.x * TILE;
    const float2* xrow = reinterpret_cast<const float2*>(x);

    // ---- front-batched loads: 8 independent LDG.64 per thread ----
    float2 xv[TILE];
    #pragma unroll
    for (int r = 0; r < TILE; ++r)
        xv[r] = xrow[(size_t)(rowbase + r) * (DIM / 2) + col2];

    // ---- packed Horner per row ----
    float acc[TILE];
    #pragma unroll
    for (int r = 0; r < TILE; ++r) {
        ull xp = pack2(xv[r].x, xv[r].y);
        ull p = A[8];
        #pragma unroll
        for (int k = 7; k >= 0; --k)
            p = fma2(p, xp, A[k]);
        float lo, hi; unpack2(p, lo, hi);
        acc[r] = lo + hi;
    }

    // ---- intra-warp reductions ----
    #pragma unroll
    for (int off = 16; off; off >>= 1) {
        #pragma unroll
        for (int r = 0; r < TILE; ++r)
            acc[r] += __shfl_xor_sync(0xffffffffu, acc[r], off);
    }
    if (lane == 0) {
        #pragma unroll
        for (int r = 0; r < TILE; ++r)
            s_part[r][w] = acc[r];
    }
    __syncthreads();

    // ---- finalize: 8 threads sum the 8 warp partials per row ----
    if (tid < TILE) {
        const float* p = s_part[tid];
        float s = ((p[0] + p[1]) + (p[2] + p[3])) + ((p[4] + p[5]) + (p[6] + p[7]));
        out[rowbase + tid] = s;
    }
}

extern "C" void kernel_launch(void* const* d_in, const int* in_sizes, int n_in,
                              void* d_out, int out_size)
{
    const float* x     = (const float*)d_in[0];
    const float* coeff = (const float*)d_in[1];
    // d_in[2] = degree (int32, fixed at 8) — baked in at compile time.
    float* out = (float*)d_out;

    kan_cheb_kernel<<<GRID, THREADS>>>(x, coeff, out);
}